// round 10
// baseline (speedup 1.0000x reference)
#include <cuda_runtime.h>
#include <cstdint>

#define T_SEQ 128
#define BATCH 512
#define DIM   128
#define NQ    8
#define NCH   32   // 4 gates * 8 wires

typedef unsigned long long u64;

// Scratch: zpre[(t*BATCH+b)*32 + ch] = x_t[b] @ Wx[:,ch], ch = gate*8+wire
__device__ float g_zpre[(size_t)T_SEQ * BATCH * NCH];
// dump target for lanes that don't own an output slot (never read)
__device__ float g_dump[64];

__device__ __forceinline__ float tanh_approx(float x) {
    float r;
    asm("tanh.approx.f32 %0, %1;" : "=f"(r) : "f"(x));
    return r;
}
__device__ __forceinline__ void ffma2(u64& acc, u64 a, u64 b) {
    asm("fma.rn.f32x2 %0, %1, %2, %0;" : "+l"(acc) : "l"(a), "l"(b));
}
__device__ __forceinline__ u64 pack2(float lo, float hi) {
    u64 r; asm("mov.b64 %0, {%1, %2};" : "=l"(r) : "f"(lo), "f"(hi)); return r;
}

// ---------------------------------------------------------------------------
// Kernel A (unchanged, proven): zpre = X @ Wx via packed f32x2 FMA.
// ---------------------------------------------------------------------------
__global__ void __launch_bounds__(128) qlstm_gemm(
    const float* __restrict__ x,
    const float* __restrict__ Wf, const float* __restrict__ Wi,
    const float* __restrict__ Wu, const float* __restrict__ Wo)
{
    __shared__ __align__(16) float ws[128][32];
    __shared__ float xs[32][129];
    const int tid  = threadIdx.x;
    const int row0 = blockIdx.x * 128;

    #pragma unroll 4
    for (int i = tid; i < 128 * 32; i += 128) {
        int k = i >> 5, j = i & 31;
        int g = j >> 3, w = j & 7;
        const float* Wg = (g == 0) ? Wf : (g == 1) ? Wi : (g == 2) ? Wu : Wo;
        ws[k][j] = Wg[k * 8 + w];
    }

    const int lane = tid & 31;
    const int c0   = (tid >> 5) * 8;

    u64 acc[4][4];
    #pragma unroll
    for (int r = 0; r < 4; r++)
        #pragma unroll
        for (int q = 0; q < 4; q++) acc[r][q] = 0ull;

    for (int kc = 0; kc < 4; ++kc) {
        __syncthreads();
        #pragma unroll 4
        for (int i = tid; i < 128 * 32; i += 128) {
            int r = i >> 5, kk = i & 31;
            xs[kk][r] = x[(size_t)(row0 + r) * DIM + kc * 32 + kk];
        }
        __syncthreads();

        #pragma unroll
        for (int k = 0; k < 32; ++k) {
            float xv0 = xs[k][lane      ];
            float xv1 = xs[k][lane + 32 ];
            float xv2 = xs[k][lane + 64 ];
            float xv3 = xs[k][lane + 96 ];
            u64 xx0 = pack2(xv0, xv0);
            u64 xx1 = pack2(xv1, xv1);
            u64 xx2 = pack2(xv2, xv2);
            u64 xx3 = pack2(xv3, xv3);
            const u64* wk = reinterpret_cast<const u64*>(&ws[kc * 32 + k][c0]);
            u64 w0 = wk[0], w1 = wk[1], w2 = wk[2], w3 = wk[3];
            ffma2(acc[0][0], xx0, w0); ffma2(acc[0][1], xx0, w1);
            ffma2(acc[0][2], xx0, w2); ffma2(acc[0][3], xx0, w3);
            ffma2(acc[1][0], xx1, w0); ffma2(acc[1][1], xx1, w1);
            ffma2(acc[1][2], xx1, w2); ffma2(acc[1][3], xx1, w3);
            ffma2(acc[2][0], xx2, w0); ffma2(acc[2][1], xx2, w1);
            ffma2(acc[2][2], xx2, w2); ffma2(acc[2][3], xx2, w3);
            ffma2(acc[3][0], xx3, w0); ffma2(acc[3][1], xx3, w1);
            ffma2(acc[3][2], xx3, w2); ffma2(acc[3][3], xx3, w3);
        }
    }

    #pragma unroll
    for (int rr = 0; rr < 4; ++rr) {
        int r = row0 + lane + 32 * rr;
        u64* dst = reinterpret_cast<u64*>(g_zpre + (size_t)r * NCH + c0);
        dst[0] = acc[rr][0]; dst[1] = acc[rr][1];
        dst[2] = acc[rr][2]; dst[3] = acc[rr][3];
    }
}

// ---------------------------------------------------------------------------
// Kernel B: recurrence, one warp per row; 15 SHFLs per step (was 20).
//   - h broadcast: 7-shfl xor-butterfly, weights pre-permuted (R8-verified)
//   - prefix products: 3-shfl masked Kogge-Stone scan (R5-verified)
//     + 2 gathers (c0, p7)
//   - gate gather: 3-shfl xor-butterfly + muxes (R8-verified)
// lane = gate*8 + wire.
// <Z_w> = prod_{k<=w} cos(phi_k) (w>=1), <Z_0> = prod_{k=1..7} cos(phi_k).
// ---------------------------------------------------------------------------
__global__ void __launch_bounds__(128) qlstm_recurrent(
    const float* __restrict__ Wf, const float* __restrict__ bf, const float* __restrict__ thf,
    const float* __restrict__ Wi, const float* __restrict__ bi, const float* __restrict__ thi,
    const float* __restrict__ Wu, const float* __restrict__ bu, const float* __restrict__ thu,
    const float* __restrict__ Wo, const float* __restrict__ bo, const float* __restrict__ tho,
    float* __restrict__ out)
{
    const int lane = threadIdx.x & 31;
    const int warp = threadIdx.x >> 5;
    const int row  = blockIdx.x * 4 + warp;       // 0..511
    const int gate = lane >> 3;
    const int wire = lane & 7;
    const int base = lane & 24;                    // gate*8

    const float* Wg = (gate == 0) ? Wf : (gate == 1) ? Wi : (gate == 2) ? Wu : Wo;
    const float* bg = (gate == 0) ? bf : (gate == 1) ? bi : (gate == 2) ? bu : bo;
    const float* tg = (gate == 0) ? thf : (gate == 1) ? thi : (gate == 2) ? thu : tho;

    // butterfly arrival order: slot j holds h_{wire ^ m[j]}
    const int m[8] = {0, 4, 2, 6, 1, 5, 3, 7};
    float whp[8];
    #pragma unroll
    for (int j = 0; j < 8; ++j)
        whp[j] = Wg[(DIM + (wire ^ m[j])) * NQ + wire];

    const float cbias = bg[wire] + tg[wire];
    const bool  isU   = (gate == 2);
    const float aScl  = isU ? 1.0f : 0.5f;
    const float aMul  = isU ? 1.0f : 0.5f;
    const float aAdd  = isU ? 0.0f : 0.5f;

    const bool w0z = (wire == 0);
    const bool q1  = (wire >= 1);
    const bool q2  = (wire >= 2);
    const bool q4  = (wire >= 4);
    const bool gb0 = (gate & 1) != 0;
    const bool gb1 = (gate & 2) != 0;

    float hv = 0.0f, cstate = 0.0f;

    // branch-free output pointer (lanes 8-31 write to dump scratch)
    float* st = (lane < 8) ? (out + (size_t)row * NQ + wire) : (g_dump + lane);
    const size_t sstr = (lane < 8) ? (size_t)(BATCH * NQ) : 0;

    const float* zp = g_zpre + (size_t)row * NCH + lane;
    const size_t tstride = (size_t)BATCH * NCH;
    float zn0 = zp[0];
    float zn1 = zp[tstride];

    const unsigned FULL = 0xffffffffu;

    #pragma unroll 1
    for (int t = 0; t < T_SEQ; ++t) {
        float zb = zn0 + cbias;
        zn0 = zn1;
        int t2 = (t + 2 < T_SEQ) ? (t + 2) : (T_SEQ - 1);
        zn1 = zp[(size_t)t2 * tstride];             // off-chain prefetch

        // --- h butterfly: 7 shfls; slot j = h_{wire^m[j]} ---
        float hs0 = hv;
        float hs1 = __shfl_xor_sync(FULL, hs0, 4);
        float hs2 = __shfl_xor_sync(FULL, hs0, 2);
        float hs3 = __shfl_xor_sync(FULL, hs1, 2);
        float hs4 = __shfl_xor_sync(FULL, hs0, 1);
        float hs5 = __shfl_xor_sync(FULL, hs1, 1);
        float hs6 = __shfl_xor_sync(FULL, hs2, 1);
        float hs7 = __shfl_xor_sync(FULL, hs3, 1);

        // z = zb + h . wh (permuted order)
        float za = fmaf(hs0, whp[0], zb);
        float zb2 = hs1 * whp[1];
        za = fmaf(hs2, whp[2], za);
        zb2 = fmaf(hs3, whp[3], zb2);
        za = fmaf(hs4, whp[4], za);
        zb2 = fmaf(hs5, whp[5], zb2);
        za = fmaf(hs6, whp[6], za);
        zb2 = fmaf(hs7, whp[7], zb2);
        float z = za + zb2;

        float c = __cosf(z);

        // --- masked Kogge-Stone segmented scan: 3 shfls ---
        float p = w0z ? 1.0f : c;
        float u;
        u = __shfl_up_sync(FULL, p, 1, 8); p = q1 ? p * u : p;
        u = __shfl_up_sync(FULL, p, 2, 8); p = q2 ? p * u : p;
        u = __shfl_up_sync(FULL, p, 4, 8); p = q4 ? p * u : p;
        // p = prod_{k=1..wire} c_k (lane0: 1)

        // --- 2 gathers: c0 and p7 of own segment ---
        float c0s = __shfl_sync(FULL, c, base);
        float p7  = __shfl_sync(FULL, p, base + 7);   // prod c1..c7
        float e   = w0z ? p7 : c0s * p;               // <Z_wire>

        float act = fmaf(aMul, tanh_approx(e * aScl), aAdd);

        // --- cross-gate act butterfly: 3 shfls ---
        float a1 = __shfl_xor_sync(FULL, act, 8);    // gate g^1
        float a2 = __shfl_xor_sync(FULL, act, 16);   // gate g^2
        float a3 = __shfl_xor_sync(FULL, a1, 16);    // gate g^3

        // mux f/i/u/o from (act, a1, a2, a3) by own gate bits
        float vf = gb1 ? (gb0 ? a3  : a2) : (gb0 ? a1  : act);
        float vi = gb1 ? (gb0 ? a2  : a3) : (gb0 ? act : a1);
        float vu = gb1 ? (gb0 ? a1  : act) : (gb0 ? a3  : a2);
        float vo = gb1 ? (gb0 ? act : a1) : (gb0 ? a2  : a3);

        cstate = fmaf(vf, cstate, vi * vu);
        hv     = vo * tanh_approx(cstate);

        *st = hv;                                     // branch-free store
        st += sstr;
    }

    if (lane < 8) {
        const size_t outs_sz = (size_t)T_SEQ * BATCH * NQ;
        out[outs_sz + (size_t)row * NQ + wire] = hv;                           // final hx
        out[outs_sz + (size_t)BATCH * NQ + (size_t)row * NQ + wire] = cstate;  // final cx
    }
}

// ---------------------------------------------------------------------------
// Launch
// ---------------------------------------------------------------------------
extern "C" void kernel_launch(void* const* d_in, const int* in_sizes, int n_in,
                              void* d_out, int out_size)
{
    const float* x   = (const float*)d_in[0];
    const float* Wf  = (const float*)d_in[1];
    const float* bf  = (const float*)d_in[2];
    const float* thf = (const float*)d_in[3];
    const float* Wi  = (const float*)d_in[4];
    const float* bi  = (const float*)d_in[5];
    const float* thi = (const float*)d_in[6];
    const float* Wu  = (const float*)d_in[7];
    const float* bu  = (const float*)d_in[8];
    const float* thu = (const float*)d_in[9];
    const float* Wo  = (const float*)d_in[10];
    const float* bo  = (const float*)d_in[11];
    const float* tho = (const float*)d_in[12];
    float* out = (float*)d_out;

    qlstm_gemm<<<(T_SEQ * BATCH) / 128, 128>>>(x, Wf, Wi, Wu, Wo);
    qlstm_recurrent<<<BATCH / 4, 128>>>(Wf, bf, thf, Wi, bi, thi,
                                        Wu, bu, thu, Wo, bo, tho, out);
}

// round 11
// speedup vs baseline: 1.4142x; 1.4142x over previous
#include <cuda_runtime.h>
#include <cstdint>

#define T_SEQ 128
#define BATCH 512
#define DIM   128
#define NQ    8
#define NCH   32   // 4 gates * 8 wires

typedef unsigned long long u64;

// Scratch: zpre[(t*BATCH+b)*32 + ch] = x_t[b] @ Wx[:,ch], ch = gate*8+wire
__device__ float g_zpre[(size_t)T_SEQ * BATCH * NCH];

__device__ __forceinline__ float tanh_approx(float x) {
    float r;
    asm("tanh.approx.f32 %0, %1;" : "=f"(r) : "f"(x));
    return r;
}
__device__ __forceinline__ void ffma2(u64& acc, u64 a, u64 b) {
    asm("fma.rn.f32x2 %0, %1, %2, %0;" : "+l"(acc) : "l"(a), "l"(b));
}
__device__ __forceinline__ u64 pack2(float lo, float hi) {
    u64 r; asm("mov.b64 %0, {%1, %2};" : "=l"(r) : "f"(lo), "f"(hi)); return r;
}

// ---------------------------------------------------------------------------
// Kernel A (unchanged, proven): zpre = X @ Wx via packed f32x2 FMA.
// ---------------------------------------------------------------------------
__global__ void __launch_bounds__(128) qlstm_gemm(
    const float* __restrict__ x,
    const float* __restrict__ Wf, const float* __restrict__ Wi,
    const float* __restrict__ Wu, const float* __restrict__ Wo)
{
    __shared__ __align__(16) float ws[128][32];
    __shared__ float xs[32][129];
    const int tid  = threadIdx.x;
    const int row0 = blockIdx.x * 128;

    #pragma unroll 4
    for (int i = tid; i < 128 * 32; i += 128) {
        int k = i >> 5, j = i & 31;
        int g = j >> 3, w = j & 7;
        const float* Wg = (g == 0) ? Wf : (g == 1) ? Wi : (g == 2) ? Wu : Wo;
        ws[k][j] = Wg[k * 8 + w];
    }

    const int lane = tid & 31;
    const int c0   = (tid >> 5) * 8;

    u64 acc[4][4];
    #pragma unroll
    for (int r = 0; r < 4; r++)
        #pragma unroll
        for (int q = 0; q < 4; q++) acc[r][q] = 0ull;

    for (int kc = 0; kc < 4; ++kc) {
        __syncthreads();
        #pragma unroll 4
        for (int i = tid; i < 128 * 32; i += 128) {
            int r = i >> 5, kk = i & 31;
            xs[kk][r] = x[(size_t)(row0 + r) * DIM + kc * 32 + kk];
        }
        __syncthreads();

        #pragma unroll
        for (int k = 0; k < 32; ++k) {
            float xv0 = xs[k][lane      ];
            float xv1 = xs[k][lane + 32 ];
            float xv2 = xs[k][lane + 64 ];
            float xv3 = xs[k][lane + 96 ];
            u64 xx0 = pack2(xv0, xv0);
            u64 xx1 = pack2(xv1, xv1);
            u64 xx2 = pack2(xv2, xv2);
            u64 xx3 = pack2(xv3, xv3);
            const u64* wk = reinterpret_cast<const u64*>(&ws[kc * 32 + k][c0]);
            u64 w0 = wk[0], w1 = wk[1], w2 = wk[2], w3 = wk[3];
            ffma2(acc[0][0], xx0, w0); ffma2(acc[0][1], xx0, w1);
            ffma2(acc[0][2], xx0, w2); ffma2(acc[0][3], xx0, w3);
            ffma2(acc[1][0], xx1, w0); ffma2(acc[1][1], xx1, w1);
            ffma2(acc[1][2], xx1, w2); ffma2(acc[1][3], xx1, w3);
            ffma2(acc[2][0], xx2, w0); ffma2(acc[2][1], xx2, w1);
            ffma2(acc[2][2], xx2, w2); ffma2(acc[2][3], xx2, w3);
            ffma2(acc[3][0], xx3, w0); ffma2(acc[3][1], xx3, w1);
            ffma2(acc[3][2], xx3, w2); ffma2(acc[3][3], xx3, w3);
        }
    }

    #pragma unroll
    for (int rr = 0; rr < 4; ++rr) {
        int r = row0 + lane + 32 * rr;
        u64* dst = reinterpret_cast<u64*>(g_zpre + (size_t)r * NCH + c0);
        dst[0] = acc[rr][0]; dst[1] = acc[rr][1];
        dst[2] = acc[rr][2]; dst[3] = acc[rr][3];
    }
}

// ---------------------------------------------------------------------------
// Kernel B: recurrence, one warp per row. EXACT frame of the proven 46us
// kernel (predicated store, unroll 2, depth-2 prefetch) with shfls cut
// 20 -> 15 via individually-verified components:
//   h broadcast:   7-shfl xor-butterfly, weights pre-permuted
//   cosine stage:  3-shfl masked Kogge-Stone scan + 2 gathers (c0, p7)
//   gate gather:   3-shfl xor-butterfly + FSEL muxes
// lane = gate*8 + wire.
// <Z_w> = prod_{k<=w} cos(phi_k) (w>=1), <Z_0> = prod_{k=1..7} cos(phi_k).
// ---------------------------------------------------------------------------
__global__ void __launch_bounds__(128) qlstm_recurrent(
    const float* __restrict__ Wf, const float* __restrict__ bf, const float* __restrict__ thf,
    const float* __restrict__ Wi, const float* __restrict__ bi, const float* __restrict__ thi,
    const float* __restrict__ Wu, const float* __restrict__ bu, const float* __restrict__ thu,
    const float* __restrict__ Wo, const float* __restrict__ bo, const float* __restrict__ tho,
    float* __restrict__ out)
{
    const int lane = threadIdx.x & 31;
    const int warp = threadIdx.x >> 5;
    const int row  = blockIdx.x * 4 + warp;       // 0..511
    const int gate = lane >> 3;
    const int wire = lane & 7;
    const int base = lane & 24;                    // gate*8

    const float* Wg = (gate == 0) ? Wf : (gate == 1) ? Wi : (gate == 2) ? Wu : Wo;
    const float* bg = (gate == 0) ? bf : (gate == 1) ? bi : (gate == 2) ? bu : bo;
    const float* tg = (gate == 0) ? thf : (gate == 1) ? thi : (gate == 2) ? thu : tho;

    // butterfly arrival order: slot j holds h_{wire ^ m[j]}
    const int m[8] = {0, 4, 2, 6, 1, 5, 3, 7};
    float whp[8];
    #pragma unroll
    for (int j = 0; j < 8; ++j)
        whp[j] = Wg[(DIM + (wire ^ m[j])) * NQ + wire];

    const float cbias = bg[wire] + tg[wire];
    const bool  isU   = (gate == 2);
    const float aScl  = isU ? 1.0f : 0.5f;
    const float aMul  = isU ? 1.0f : 0.5f;
    const float aAdd  = isU ? 0.0f : 0.5f;

    const bool w0z = (wire == 0);
    const bool q1  = (wire >= 1);
    const bool q2  = (wire >= 2);
    const bool q4  = (wire >= 4);
    const bool gb0 = (gate & 1) != 0;
    const bool gb1 = (gate & 2) != 0;

    float hv = 0.0f, cstate = 0.0f;

    const float* zp = g_zpre + (size_t)row * NCH + lane;
    const size_t tstride = (size_t)BATCH * NCH;
    float zn0 = zp[0];
    float zn1 = zp[tstride];

    float* outw = out + (size_t)row * NQ + wire;   // step stride = BATCH*NQ

    const unsigned FULL = 0xffffffffu;

    #pragma unroll 2
    for (int t = 0; t < T_SEQ; ++t) {
        float zb = zn0 + cbias;
        zn0 = zn1;
        int t2 = (t + 2 < T_SEQ) ? (t + 2) : (T_SEQ - 1);
        zn1 = zp[(size_t)t2 * tstride];             // off-chain prefetch

        // --- h butterfly: 7 shfls; slot j = h_{wire^m[j]} ---
        float hs0 = hv;
        float hs1 = __shfl_xor_sync(FULL, hs0, 4);
        float hs2 = __shfl_xor_sync(FULL, hs0, 2);
        float hs3 = __shfl_xor_sync(FULL, hs1, 2);
        float hs4 = __shfl_xor_sync(FULL, hs0, 1);
        float hs5 = __shfl_xor_sync(FULL, hs1, 1);
        float hs6 = __shfl_xor_sync(FULL, hs2, 1);
        float hs7 = __shfl_xor_sync(FULL, hs3, 1);

        // z = zb + h . wh (permuted order, two parallel FMA chains)
        float za  = fmaf(hs0, whp[0], zb);
        float zb2 = hs1 * whp[1];
        za  = fmaf(hs2, whp[2], za);
        zb2 = fmaf(hs3, whp[3], zb2);
        za  = fmaf(hs4, whp[4], za);
        zb2 = fmaf(hs5, whp[5], zb2);
        za  = fmaf(hs6, whp[6], za);
        zb2 = fmaf(hs7, whp[7], zb2);
        float z = za + zb2;

        float c = __cosf(z);

        // --- masked Kogge-Stone segmented scan: 3 shfls ---
        float p = w0z ? 1.0f : c;
        float u;
        u = __shfl_up_sync(FULL, p, 1, 8); p = q1 ? p * u : p;
        u = __shfl_up_sync(FULL, p, 2, 8); p = q2 ? p * u : p;
        u = __shfl_up_sync(FULL, p, 4, 8); p = q4 ? p * u : p;
        // p = prod_{k=1..wire} c_k (lane0: 1)

        // --- 2 gathers: c0 and p7 of own segment ---
        float c0s = __shfl_sync(FULL, c, base);
        float p7  = __shfl_sync(FULL, p, base + 7);   // prod c1..c7
        float e   = w0z ? p7 : c0s * p;               // <Z_wire>

        float act = fmaf(aMul, tanh_approx(e * aScl), aAdd);

        // --- cross-gate act butterfly: 3 shfls ---
        float a1 = __shfl_xor_sync(FULL, act, 8);    // gate g^1
        float a2 = __shfl_xor_sync(FULL, act, 16);   // gate g^2
        float a3 = __shfl_xor_sync(FULL, a1, 16);    // gate g^3

        // mux f/i/u/o from (act, a1, a2, a3) by own gate bits
        float vf = gb1 ? (gb0 ? a3  : a2) : (gb0 ? a1  : act);
        float vi = gb1 ? (gb0 ? a2  : a3) : (gb0 ? act : a1);
        float vu = gb1 ? (gb0 ? a1  : act) : (gb0 ? a3  : a2);
        float vo = gb1 ? (gb0 ? act : a1) : (gb0 ? a2  : a3);

        cstate = fmaf(vf, cstate, vi * vu);
        hv     = vo * tanh_approx(cstate);

        if (lane < 8)
            outw[(size_t)t * (BATCH * NQ)] = hv;      // predicated store
    }

    if (lane < 8) {
        const size_t outs_sz = (size_t)T_SEQ * BATCH * NQ;
        out[outs_sz + (size_t)row * NQ + wire] = hv;                           // final hx
        out[outs_sz + (size_t)BATCH * NQ + (size_t)row * NQ + wire] = cstate;  // final cx
    }
}

// ---------------------------------------------------------------------------
// Launch
// ---------------------------------------------------------------------------
extern "C" void kernel_launch(void* const* d_in, const int* in_sizes, int n_in,
                              void* d_out, int out_size)
{
    const float* x   = (const float*)d_in[0];
    const float* Wf  = (const float*)d_in[1];
    const float* bf  = (const float*)d_in[2];
    const float* thf = (const float*)d_in[3];
    const float* Wi  = (const float*)d_in[4];
    const float* bi  = (const float*)d_in[5];
    const float* thi = (const float*)d_in[6];
    const float* Wu  = (const float*)d_in[7];
    const float* bu  = (const float*)d_in[8];
    const float* thu = (const float*)d_in[9];
    const float* Wo  = (const float*)d_in[10];
    const float* bo  = (const float*)d_in[11];
    const float* tho = (const float*)d_in[12];
    float* out = (float*)d_out;

    qlstm_gemm<<<(T_SEQ * BATCH) / 128, 128>>>(x, Wf, Wi, Wu, Wo);
    qlstm_recurrent<<<BATCH / 4, 128>>>(Wf, bf, thf, Wi, bi, thi,
                                        Wu, bu, thu, Wo, bo, tho, out);
}